// round 7
// baseline (speedup 1.0000x reference)
#include <cuda_runtime.h>
#include <cuda_bf16.h>
#include <stdint.h>
#include <math.h>

#define B_  8
#define S_  1024
#define D_  1024
#define H_  16
#define DH_ 64
#define M_  (B_*S_)     // 8192

// Projected split planes
__device__ __nv_bfloat16 g_qh[(size_t)M_*D_], g_ql[(size_t)M_*D_];
__device__ __nv_bfloat16 g_kh[(size_t)M_*D_], g_kl[(size_t)M_*D_];
__device__ __nv_bfloat16 g_vh[(size_t)M_*D_], g_vl[(size_t)M_*D_];
__device__ __nv_bfloat16 g_ch[(size_t)M_*D_], g_cl[(size_t)M_*D_];
// Raw-input split planes
__device__ __nv_bfloat16 g_rqh[(size_t)M_*D_], g_rql[(size_t)M_*D_];
__device__ __nv_bfloat16 g_rkh[(size_t)M_*D_], g_rkl[(size_t)M_*D_];
__device__ __nv_bfloat16 g_rvh[(size_t)M_*D_], g_rvl[(size_t)M_*D_];
// Weight split planes (wq, wk, wv, wo)
__device__ __nv_bfloat16 g_wh[4][(size_t)D_*D_], g_wl[4][(size_t)D_*D_];

// ---------------------------------------------------------------------------
__device__ __forceinline__ uint32_t cvta_s(const void* p) {
    return (uint32_t)__cvta_generic_to_shared(p);
}
__device__ __forceinline__ void cpa16(uint32_t dst, const void* src) {
    asm volatile("cp.async.cg.shared.global [%0], [%1], 16;" :: "r"(dst), "l"(src));
}
__device__ __forceinline__ void ldsm4(uint32_t r[4], uint32_t a) {
    asm volatile("ldmatrix.sync.aligned.m8n8.x4.shared.b16 {%0,%1,%2,%3}, [%4];"
        : "=r"(r[0]), "=r"(r[1]), "=r"(r[2]), "=r"(r[3]) : "r"(a));
}
__device__ __forceinline__ void ldsm4t(uint32_t r[4], uint32_t a) {
    asm volatile("ldmatrix.sync.aligned.m8n8.x4.trans.shared.b16 {%0,%1,%2,%3}, [%4];"
        : "=r"(r[0]), "=r"(r[1]), "=r"(r[2]), "=r"(r[3]) : "r"(a));
}
__device__ __forceinline__ void mma_bf(float c[4], const uint32_t a[4],
                                       uint32_t b0, uint32_t b1) {
    asm volatile("mma.sync.aligned.m16n8k16.row.col.f32.bf16.bf16.f32 "
        "{%0,%1,%2,%3},{%4,%5,%6,%7},{%8,%9},{%0,%1,%2,%3};"
        : "+f"(c[0]), "+f"(c[1]), "+f"(c[2]), "+f"(c[3])
        : "r"(a[0]), "r"(a[1]), "r"(a[2]), "r"(a[3]), "r"(b0), "r"(b1));
}
__device__ __forceinline__ void split_bf(float x, __nv_bfloat16& h, __nv_bfloat16& l) {
    h = __float2bfloat16(x);
    l = __float2bfloat16(x - __bfloat162float(h));
}
// pack two floats into bf16 hi-pair and lo-pair regs
__device__ __forceinline__ void split2(float x, float y, uint32_t& h, uint32_t& l) {
    __nv_bfloat16 hx, lx, hy, ly;
    split_bf(x, hx, lx); split_bf(y, hy, ly);
    __nv_bfloat162 hh = __halves2bfloat162(hx, hy);
    __nv_bfloat162 ll = __halves2bfloat162(lx, ly);
    h = *(uint32_t*)&hh; l = *(uint32_t*)&ll;
}

// ---------------------------------------------------------------------------
// Pre-split: fp32 -> bf16 hi/lo planes
// ---------------------------------------------------------------------------
__global__ void __launch_bounds__(256)
split_kernel(const float* __restrict__ in, __nv_bfloat16* __restrict__ hi,
             __nv_bfloat16* __restrict__ lo, int n4)
{
    int i = blockIdx.x * blockDim.x + threadIdx.x;
    if (i >= n4) return;
    float4 v = ((const float4*)in)[i];
    __nv_bfloat16 h0,l0,h1,l1,h2,l2,h3,l3;
    split_bf(v.x,h0,l0); split_bf(v.y,h1,l1);
    split_bf(v.z,h2,l2); split_bf(v.w,h3,l3);
    ((__nv_bfloat162*)hi)[2*i]   = __halves2bfloat162(h0,h1);
    ((__nv_bfloat162*)hi)[2*i+1] = __halves2bfloat162(h2,h3);
    ((__nv_bfloat162*)lo)[2*i]   = __halves2bfloat162(l0,l1);
    ((__nv_bfloat162*)lo)[2*i+1] = __halves2bfloat162(l2,l3);
}

// ---------------------------------------------------------------------------
// Big GEMM (round-5 proven): C = epi(A @ W + bias), all-split, cp.async 2-stage
// ---------------------------------------------------------------------------
#define STG_ 18944
template<bool DO_BN, bool SPLIT_OUT>
__global__ void __launch_bounds__(256)
gemm_tc2(const __nv_bfloat16* __restrict__ Ah, const __nv_bfloat16* __restrict__ Al,
         const __nv_bfloat16* __restrict__ Wh, const __nv_bfloat16* __restrict__ Wl,
         const float* __restrict__ bias,
         const float* __restrict__ gam, const float* __restrict__ bet,
         const float* __restrict__ mmean, const float* __restrict__ mvar,
         float* __restrict__ Cf,
         __nv_bfloat16* __restrict__ Chg, __nv_bfloat16* __restrict__ Clg)
{
    extern __shared__ __align__(16) __nv_bfloat16 sm2[];
    const int tid = threadIdx.x, lane = tid & 31, warp = tid >> 5;
    const int brow = blockIdx.y * 128, bcol = blockIdx.x * 128;

    auto issue = [&](int slab, int buf) {
        __nv_bfloat16* st = sm2 + buf * STG_;
        const int ks = slab * 32;
        #pragma unroll
        for (int p = 0; p < 2; p++) {
            int c = tid + 256 * p;
            int r = c >> 2, q = (c & 3) * 8;
            const size_t ga = (size_t)(brow + r) * D_ + ks + q;
            cpa16(cvta_s(&st[r*40 + q]),        &Ah[ga]);
            cpa16(cvta_s(&st[5120 + r*40 + q]), &Al[ga]);
        }
        #pragma unroll
        for (int p = 0; p < 2; p++) {
            int c = tid + 256 * p;
            int r = c >> 4, q = (c & 15) * 8;
            const size_t gb = (size_t)(ks + r) * D_ + bcol + q;
            cpa16(cvta_s(&st[10240 + r*136 + q]), &Wh[gb]);
            cpa16(cvta_s(&st[14592 + r*136 + q]), &Wl[gb]);
        }
        asm volatile("cp.async.commit_group;");
    };

    const int wm = warp >> 1, wn = warp & 1;
    const int m0 = wm * 32, n0 = wn * 64;

    float acc[2][8][4];
    #pragma unroll
    for (int i = 0; i < 2; i++)
        #pragma unroll
        for (int j = 0; j < 8; j++)
            #pragma unroll
            for (int q = 0; q < 4; q++) acc[i][j][q] = 0.f;

    issue(0, 0);
    for (int s = 0; s < 32; s++) {
        const int buf = s & 1;
        if (s + 1 < 32) {
            issue(s + 1, buf ^ 1);
            asm volatile("cp.async.wait_group 1;");
        } else {
            asm volatile("cp.async.wait_group 0;");
        }
        __syncthreads();

        const __nv_bfloat16* sAh = sm2 + buf * STG_;
        const __nv_bfloat16* sAl = sAh + 5120;
        const __nv_bfloat16* sBh = sAh + 10240;
        const __nv_bfloat16* sBl = sAh + 14592;

        #pragma unroll
        for (int kk = 0; kk < 32; kk += 16) {
            uint32_t ah[2][4], al[2][4];
            #pragma unroll
            for (int mi = 0; mi < 2; mi++) {
                int off = (m0 + mi*16 + (lane & 15)) * 40 + kk + ((lane >> 4) << 3);
                ldsm4(ah[mi], cvta_s(&sAh[off]));
                ldsm4(al[mi], cvta_s(&sAl[off]));
            }
            #pragma unroll
            for (int nj = 0; nj < 4; nj++) {
                uint32_t bh[4], bl[4];
                int off = (kk + (lane & 15)) * 136 + n0 + nj*16 + ((lane >> 4) << 3);
                ldsm4t(bh, cvta_s(&sBh[off]));
                ldsm4t(bl, cvta_s(&sBl[off]));
                #pragma unroll
                for (int mi = 0; mi < 2; mi++) {
                    mma_bf(acc[mi][2*nj],   ah[mi], bh[0], bh[1]);
                    mma_bf(acc[mi][2*nj],   ah[mi], bl[0], bl[1]);
                    mma_bf(acc[mi][2*nj],   al[mi], bh[0], bh[1]);
                    mma_bf(acc[mi][2*nj+1], ah[mi], bh[2], bh[3]);
                    mma_bf(acc[mi][2*nj+1], ah[mi], bl[2], bl[3]);
                    mma_bf(acc[mi][2*nj+1], al[mi], bh[2], bh[3]);
                }
            }
        }
        __syncthreads();
    }

    #pragma unroll
    for (int mi = 0; mi < 2; mi++) {
        int r0 = brow + m0 + mi*16 + (lane >> 2);
        #pragma unroll
        for (int nj = 0; nj < 8; nj++) {
            int c = bcol + n0 + nj*8 + (lane & 3)*2;
            float b0v = bias[c], b1v = bias[c+1];
            float sc0 = 1.f, sh0 = 0.f, sc1 = 1.f, sh1 = 0.f;
            if (DO_BN) {
                sc0 = gam[c]   * rsqrtf(mvar[c]   + 1e-3f); sh0 = bet[c]   - mmean[c]   * sc0;
                sc1 = gam[c+1] * rsqrtf(mvar[c+1] + 1e-3f); sh1 = bet[c+1] - mmean[c+1] * sc1;
            }
            float y00 = fmaxf(acc[mi][nj][0] + b0v, 0.f);
            float y01 = fmaxf(acc[mi][nj][1] + b1v, 0.f);
            float y10 = fmaxf(acc[mi][nj][2] + b0v, 0.f);
            float y11 = fmaxf(acc[mi][nj][3] + b1v, 0.f);
            if (DO_BN) {
                y00 = y00*sc0 + sh0; y01 = y01*sc1 + sh1;
                y10 = y10*sc0 + sh0; y11 = y11*sc1 + sh1;
            }
            if constexpr (SPLIT_OUT) {
                __nv_bfloat16 h0,l0,h1,l1,h2,l2,h3,l3;
                split_bf(y00,h0,l0); split_bf(y01,h1,l1);
                split_bf(y10,h2,l2); split_bf(y11,h3,l3);
                *(__nv_bfloat162*)&Chg[(size_t)r0*D_ + c]     = __halves2bfloat162(h0,h1);
                *(__nv_bfloat162*)&Clg[(size_t)r0*D_ + c]     = __halves2bfloat162(l0,l1);
                *(__nv_bfloat162*)&Chg[(size_t)(r0+8)*D_ + c] = __halves2bfloat162(h2,h3);
                *(__nv_bfloat162*)&Clg[(size_t)(r0+8)*D_ + c] = __halves2bfloat162(l2,l3);
            } else {
                *(float2*)&Cf[(size_t)r0*D_ + c]     = make_float2(y00, y01);
                *(float2*)&Cf[(size_t)(r0+8)*D_ + c] = make_float2(y10, y11);
            }
        }
    }
}

// ---------------------------------------------------------------------------
// Fused attention, register-resident P.
// CTA = 16 query rows x one (b,h); 256 threads (8 warps).
// Warp wn owns n16 chunks {8j+wn : j=0..7} -> every 128-col tile feeds all warps.
// Phase 1: scores (Q regs x K tiles) -> acc[8][2][4] (full 16x1024 rows in regs)
// Softmax in regs (shfl + small smem), attn written ONCE.
// Phase 2: ctx partials (P regs x V tiles) -> smem atomicAdd reduce -> split out.
// K/V tiles: cp.async double buffer, [128][88] bf16 per plane (176B rows).
// ---------------------------------------------------------------------------
#define TSTR   88                      // tile row stride (elems), 176B (16B-mult, ldsm-clean)
#define TPL    22528                   // bytes per plane (128*176)
#define TBUF   45056                   // bytes per buffer (2 planes)
#define OFF_Q  90112                   // sQh (16*72*2 = 2304B), sQl at +2304
#define OFF_M  94720                   // mask 1024 f32
#define OFF_RM 98816                   // sRmax [16][8]
#define OFF_RS 99328                   // sRsum [16][8]
#define OFF_CX 99840                   // sCtx 16*64 f32
#define FSMEM  103936

__global__ void __launch_bounds__(256, 2)
fattn(const float* __restrict__ mask, float* __restrict__ attn)
{
    extern __shared__ __align__(16) char smb[];
    __nv_bfloat16* sQh = (__nv_bfloat16*)(smb + OFF_Q);
    __nv_bfloat16* sQl = (__nv_bfloat16*)(smb + OFF_Q + 2304);
    float* msk   = (float*)(smb + OFF_M);
    float* sRmax = (float*)(smb + OFF_RM);
    float* sRsum = (float*)(smb + OFF_RS);
    float* sCtx  = (float*)(smb + OFF_CX);

    const int bh = blockIdx.y, b = bh >> 4, h = bh & 15;
    const int brow = blockIdx.x * 16;
    const size_t base = (size_t)b * S_ * D_ + h * DH_;
    const int tid = threadIdx.x, lane = tid & 31, wn = tid >> 5;

    // Q (16x64 hi/lo), mask, zero ctx buffer
    if (tid < 128) {
        int row = tid >> 3, ch = (tid & 7) * 8;
        *(uint4*)&sQh[row*72 + ch] = *(const uint4*)&g_qh[base + (size_t)(brow+row)*D_ + ch];
    } else {
        int t2 = tid - 128;
        int row = t2 >> 3, ch = (t2 & 7) * 8;
        *(uint4*)&sQl[row*72 + ch] = *(const uint4*)&g_ql[base + (size_t)(brow+row)*D_ + ch];
    }
    {
        float4 mv = *(const float4*)&mask[b*S_ + tid*4];
        *(float4*)&msk[tid*4] = make_float4(mv.x*-1e9f, mv.y*-1e9f, mv.z*-1e9f, mv.w*-1e9f);
    }
    *(float4*)&sCtx[tid*4] = make_float4(0.f, 0.f, 0.f, 0.f);

    auto issueT = [&](const __nv_bfloat16* __restrict__ gh,
                      const __nv_bfloat16* __restrict__ gl, int t, int buf) {
        uint32_t sb = cvta_s(smb) + buf * TBUF;
        #pragma unroll
        for (int p = 0; p < 4; p++) {
            int idx = tid + 256 * p;          // 0..1023
            int r = idx >> 3, ch = idx & 7;
            size_t g = base + (size_t)(t*128 + r) * D_ + ch * 8;
            cpa16(sb +       r*176 + ch*16, &gh[g]);
            cpa16(sb + TPL + r*176 + ch*16, &gl[g]);
        }
        asm volatile("cp.async.commit_group;");
    };

    // ---- phase 1: scores ----
    float acc[8][2][4];
    uint32_t qh[4][4], ql[4][4];

    issueT(g_kh, g_kl, 0, 0);
    for (int kt = 0; kt < 8; kt++) {
        if (kt < 7) issueT(g_kh, g_kl, kt + 1, (kt + 1) & 1);
        else        issueT(g_vh, g_vl, 0, 0);
        asm volatile("cp.async.wait_group 1;");
        __syncthreads();
        if (kt == 0) {  // Q frags (sQ ready after first sync)
            #pragma unroll
            for (int t4 = 0; t4 < 4; t4++) {
                int off = (lane & 15) * 72 + t4*16 + ((lane >> 4) << 3);
                ldsm4(qh[t4], cvta_s(&sQh[off]));
                ldsm4(ql[t4], cvta_s(&sQl[off]));
            }
        }
        const __nv_bfloat16* Th = (const __nv_bfloat16*)(smb + (kt & 1) * TBUF);
        const __nv_bfloat16* Tl = (const __nv_bfloat16*)(smb + (kt & 1) * TBUF + TPL);

        #pragma unroll
        for (int q4 = 0; q4 < 4; q4++) acc[kt][0][q4] = acc[kt][1][q4] = 0.f;
        #pragma unroll
        for (int k4 = 0; k4 < 4; k4++) {
            int kk = k4 * 16;
            int nr = 16*wn + ((lane & 7) | (((lane >> 4) & 1) << 3));
            int off = nr * TSTR + kk + (((lane >> 3) & 1) << 3);
            uint32_t bhf[4], blf[4];
            ldsm4(bhf, cvta_s(&Th[off]));
            ldsm4(blf, cvta_s(&Tl[off]));
            mma_bf(acc[kt][0], qh[k4], bhf[0], bhf[1]);
            mma_bf(acc[kt][0], qh[k4], blf[0], blf[1]);
            mma_bf(acc[kt][0], ql[k4], bhf[0], bhf[1]);
            mma_bf(acc[kt][1], qh[k4], bhf[2], bhf[3]);
            mma_bf(acc[kt][1], qh[k4], blf[2], blf[3]);
            mma_bf(acc[kt][1], ql[k4], bhf[2], bhf[3]);
        }
        __syncthreads();
    }

    // ---- softmax over full 1024 cols (rows ra, ra+8) ----
    const int ra = lane >> 2;
    float mxA = -3.4e38f, mxB = -3.4e38f;
    #pragma unroll
    for (int j = 0; j < 8; j++)
        #pragma unroll
        for (int t = 0; t < 2; t++) {
            int c = (8*j + wn)*16 + t*8 + (lane & 3)*2;
            float m0 = msk[c], m1 = msk[c+1];
            acc[j][t][0] = acc[j][t][0]*0.125f + m0;
            acc[j][t][1] = acc[j][t][1]*0.125f + m1;
            acc[j][t][2] = acc[j][t][2]*0.125f + m0;
            acc[j][t][3] = acc[j][t][3]*0.125f + m1;
            mxA = fmaxf(mxA, fmaxf(acc[j][t][0], acc[j][t][1]));
            mxB = fmaxf(mxB, fmaxf(acc[j][t][2], acc[j][t][3]));
        }
    #pragma unroll
    for (int o = 1; o < 4; o <<= 1) {
        mxA = fmaxf(mxA, __shfl_xor_sync(0xffffffffu, mxA, o));
        mxB = fmaxf(mxB, __shfl_xor_sync(0xffffffffu, mxB, o));
    }
    if ((lane & 3) == 0) { sRmax[ra*8 + wn] = mxA; sRmax[(ra+8)*8 + wn] = mxB; }
    __syncthreads();
    mxA = sRmax[ra*8]; mxB = sRmax[(ra+8)*8];
    #pragma unroll
    for (int i = 1; i < 8; i++) {
        mxA = fmaxf(mxA, sRmax[ra*8 + i]);
        mxB = fmaxf(mxB, sRmax[(ra+8)*8 + i]);
    }
    float sA = 0.f, sB = 0.f;
    #pragma unroll
    for (int j = 0; j < 8; j++)
        #pragma unroll
        for (int t = 0; t < 2; t++) {
            acc[j][t][0] = __expf(acc[j][t][0] - mxA);
            acc[j][t][1] = __expf(acc[j][t][1] - mxA);
            acc[j][t][2] = __expf(acc[j][t][2] - mxB);
            acc[j][t][3] = __expf(acc[j][t][3] - mxB);
            sA += acc[j][t][0] + acc[j][t][1];
            sB += acc[j][t][2] + acc[j][t][3];
        }
    #pragma unroll
    for (int o = 1; o < 4; o <<= 1) {
        sA += __shfl_xor_sync(0xffffffffu, sA, o);
        sB += __shfl_xor_sync(0xffffffffu, sB, o);
    }
    if ((lane & 3) == 0) { sRsum[ra*8 + wn] = sA; sRsum[(ra+8)*8 + wn] = sB; }
    __syncthreads();
    sA = 0.f; sB = 0.f;
    #pragma unroll
    for (int i = 0; i < 8; i++) { sA += sRsum[ra*8 + i]; sB += sRsum[(ra+8)*8 + i]; }
    const float invA = 1.f / sA, invB = 1.f / sB;

    // normalize in regs, write attn once
    float* op = attn + (size_t)bh * S_ * S_;
    #pragma unroll
    for (int j = 0; j < 8; j++)
        #pragma unroll
        for (int t = 0; t < 2; t++) {
            int c = (8*j + wn)*16 + t*8 + (lane & 3)*2;
            acc[j][t][0] *= invA; acc[j][t][1] *= invA;
            acc[j][t][2] *= invB; acc[j][t][3] *= invB;
            *(float2*)&op[(size_t)(brow + ra)*S_ + c]     = make_float2(acc[j][t][0], acc[j][t][1]);
            *(float2*)&op[(size_t)(brow + ra + 8)*S_ + c] = make_float2(acc[j][t][2], acc[j][t][3]);
        }

    // ---- phase 2: ctx = P @ V (warp covers k in its chunks; partials reduced) ----
    float cacc[8][4];
    #pragma unroll
    for (int nj = 0; nj < 8; nj++)
        #pragma unroll
        for (int q4 = 0; q4 < 4; q4++) cacc[nj][q4] = 0.f;

    for (int vt = 0; vt < 8; vt++) {
        if (vt < 7) issueT(g_vh, g_vl, vt + 1, (vt + 1) & 1);
        if (vt < 7) asm volatile("cp.async.wait_group 1;");
        else        asm volatile("cp.async.wait_group 0;");
        __syncthreads();
        const __nv_bfloat16* Th = (const __nv_bfloat16*)(smb + (vt & 1) * TBUF);
        const __nv_bfloat16* Tl = (const __nv_bfloat16*)(smb + (vt & 1) * TBUF + TPL);

        // A-frags from P chunk j=vt (C-frag -> A-frag identity), split hi/lo
        uint32_t ah[4], al[4];
        split2(acc[vt][0][0], acc[vt][0][1], ah[0], al[0]);
        split2(acc[vt][0][2], acc[vt][0][3], ah[1], al[1]);
        split2(acc[vt][1][0], acc[vt][1][1], ah[2], al[2]);
        split2(acc[vt][1][2], acc[vt][1][3], ah[3], al[3]);

        #pragma unroll
        for (int n4 = 0; n4 < 4; n4++) {
            int n0 = n4 * 16;
            int off = (16*wn + (lane & 15)) * TSTR + n0 + ((lane >> 4) << 3);
            uint32_t bhf[4], blf[4];
            ldsm4t(bhf, cvta_s(&Th[off]));
            ldsm4t(blf, cvta_s(&Tl[off]));
            mma_bf(cacc[2*n4],   ah, bhf[0], bhf[1]);
            mma_bf(cacc[2*n4],   ah, blf[0], blf[1]);
            mma_bf(cacc[2*n4],   al, bhf[0], bhf[1]);
            mma_bf(cacc[2*n4+1], ah, bhf[2], bhf[3]);
            mma_bf(cacc[2*n4+1], ah, blf[2], blf[3]);
            mma_bf(cacc[2*n4+1], al, bhf[2], bhf[3]);
        }
        __syncthreads();
    }

    // reduce 8 warp-partials via smem atomics
    #pragma unroll
    for (int nj = 0; nj < 8; nj++) {
        int c = nj*8 + (lane & 3)*2;
        atomicAdd(&sCtx[ra*64 + c],       cacc[nj][0]);
        atomicAdd(&sCtx[ra*64 + c + 1],   cacc[nj][1]);
        atomicAdd(&sCtx[(ra+8)*64 + c],   cacc[nj][2]);
        atomicAdd(&sCtx[(ra+8)*64 + c+1], cacc[nj][3]);
    }
    __syncthreads();

    // split-store ctx (16x64) to g_ch/g_cl
    {
        int i = tid * 4;                 // 0..1020
        int r = i >> 6, c = i & 63;
        float x0 = sCtx[r*64 + c],     x1 = sCtx[r*64 + c + 1];
        float x2 = sCtx[r*64 + c + 2], x3 = sCtx[r*64 + c + 3];
        __nv_bfloat16 h0,l0,h1,l1,h2,l2,h3,l3;
        split_bf(x0,h0,l0); split_bf(x1,h1,l1);
        split_bf(x2,h2,l2); split_bf(x3,h3,l3);
        size_t go = base + (size_t)(brow + r) * D_ + c;
        *(__nv_bfloat162*)&g_ch[go]     = __halves2bfloat162(h0,h1);
        *(__nv_bfloat162*)&g_ch[go + 2] = __halves2bfloat162(h2,h3);
        *(__nv_bfloat162*)&g_cl[go]     = __halves2bfloat162(l0,l1);
        *(__nv_bfloat162*)&g_cl[go + 2] = __halves2bfloat162(l2,l3);
    }
}

// ---------------------------------------------------------------------------
extern "C" void kernel_launch(void* const* d_in, const int* in_sizes, int n_in,
                              void* d_out, int out_size)
{
    const float* q    = (const float*)d_in[0];
    const float* k    = (const float*)d_in[1];
    const float* v    = (const float*)d_in[2];
    const float* mask = (const float*)d_in[3];
    const float* wq = (const float*)d_in[4];  const float* bq = (const float*)d_in[5];
    const float* wk = (const float*)d_in[6];  const float* bk = (const float*)d_in[7];
    const float* wv = (const float*)d_in[8];  const float* bv = (const float*)d_in[9];
    const float* wo = (const float*)d_in[10]; const float* bo = (const float*)d_in[11];
    const float* g1 = (const float*)d_in[12]; const float* be1 = (const float*)d_in[13];
    const float* mm1 = (const float*)d_in[14]; const float* mv1 = (const float*)d_in[15];
    const float* g2 = (const float*)d_in[16]; const float* be2 = (const float*)d_in[17];
    const float* mm2 = (const float*)d_in[18]; const float* mv2 = (const float*)d_in[19];
    const float* g3 = (const float*)d_in[20]; const float* be3 = (const float*)d_in[21];
    const float* mm3 = (const float*)d_in[22]; const float* mv3 = (const float*)d_in[23];

    float* out  = (float*)d_out;
    float* attn = out + (size_t)M_ * D_;

    void* p;
    __nv_bfloat16 *qh,*ql,*kh,*kl,*vh,*vl,*ch,*cl;
    __nv_bfloat16 *rqh,*rql,*rkh,*rkl,*rvh,*rvl,*wph,*wpl;
    cudaGetSymbolAddress(&p, g_qh); qh = (__nv_bfloat16*)p;
    cudaGetSymbolAddress(&p, g_ql); ql = (__nv_bfloat16*)p;
    cudaGetSymbolAddress(&p, g_kh); kh = (__nv_bfloat16*)p;
    cudaGetSymbolAddress(&p, g_kl); kl = (__nv_bfloat16*)p;
    cudaGetSymbolAddress(&p, g_vh); vh = (__nv_bfloat16*)p;
    cudaGetSymbolAddress(&p, g_vl); vl = (__nv_bfloat16*)p;
    cudaGetSymbolAddress(&p, g_ch); ch = (__nv_bfloat16*)p;
    cudaGetSymbolAddress(&p, g_cl); cl = (__nv_bfloat16*)p;
    cudaGetSymbolAddress(&p, g_rqh); rqh = (__nv_bfloat16*)p;
    cudaGetSymbolAddress(&p, g_rql); rql = (__nv_bfloat16*)p;
    cudaGetSymbolAddress(&p, g_rkh); rkh = (__nv_bfloat16*)p;
    cudaGetSymbolAddress(&p, g_rkl); rkl = (__nv_bfloat16*)p;
    cudaGetSymbolAddress(&p, g_rvh); rvh = (__nv_bfloat16*)p;
    cudaGetSymbolAddress(&p, g_rvl); rvl = (__nv_bfloat16*)p;
    cudaGetSymbolAddress(&p, g_wh); wph = (__nv_bfloat16*)p;
    cudaGetSymbolAddress(&p, g_wl); wpl = (__nv_bfloat16*)p;

    const size_t WSZ = (size_t)D_ * D_;
    const int n4a = (int)((size_t)M_ * D_ / 4);
    const int n4w = (int)(WSZ / 4);

    split_kernel<<<n4a/256, 256>>>(q, rqh, rql, n4a);
    split_kernel<<<n4a/256, 256>>>(k, rkh, rkl, n4a);
    split_kernel<<<n4a/256, 256>>>(v, rvh, rvl, n4a);
    split_kernel<<<n4w/256, 256>>>(wq, wph + 0*WSZ, wpl + 0*WSZ, n4w);
    split_kernel<<<n4w/256, 256>>>(wk, wph + 1*WSZ, wpl + 1*WSZ, n4w);
    split_kernel<<<n4w/256, 256>>>(wv, wph + 2*WSZ, wpl + 2*WSZ, n4w);
    split_kernel<<<n4w/256, 256>>>(wo, wph + 3*WSZ, wpl + 3*WSZ, n4w);

    cudaFuncSetAttribute(gemm_tc2<true,true>,
        cudaFuncAttributeMaxDynamicSharedMemorySize, 2*STG_*2);
    cudaFuncSetAttribute(gemm_tc2<false,false>,
        cudaFuncAttributeMaxDynamicSharedMemorySize, 2*STG_*2);
    cudaFuncSetAttribute(fattn, cudaFuncAttributeMaxDynamicSharedMemorySize, FSMEM);

    dim3 gp(D_/128, M_/128);   // (8, 64)
    gemm_tc2<true,true><<<gp,256,2*STG_*2>>>(rqh, rql, wph + 0*WSZ, wpl + 0*WSZ,
        bq, g1, be1, mm1, mv1, nullptr, qh, ql);
    gemm_tc2<true,true><<<gp,256,2*STG_*2>>>(rkh, rkl, wph + 1*WSZ, wpl + 1*WSZ,
        bk, g2, be2, mm2, mv2, nullptr, kh, kl);
    gemm_tc2<true,true><<<gp,256,2*STG_*2>>>(rvh, rvl, wph + 2*WSZ, wpl + 2*WSZ,
        bv, g3, be3, mm3, mv3, nullptr, vh, vl);

    fattn<<<dim3(S_/16, B_*H_), 256, FSMEM>>>(mask, attn);

    gemm_tc2<false,false><<<gp,256,2*STG_*2>>>(ch, cl, wph + 3*WSZ, wpl + 3*WSZ,
        bo, nullptr, nullptr, nullptr, nullptr, out, nullptr, nullptr);
}

// round 8
// speedup vs baseline: 1.1986x; 1.1986x over previous
#include <cuda_runtime.h>
#include <cuda_bf16.h>
#include <stdint.h>
#include <math.h>

#define B_  8
#define S_  1024
#define D_  1024
#define H_  16
#define DH_ 64
#define M_  (B_*S_)     // 8192

// Projected split planes
__device__ __nv_bfloat16 g_qh[(size_t)M_*D_], g_ql[(size_t)M_*D_];
__device__ __nv_bfloat16 g_kh[(size_t)M_*D_], g_kl[(size_t)M_*D_];
__device__ __nv_bfloat16 g_vh[(size_t)M_*D_], g_vl[(size_t)M_*D_];
__device__ __nv_bfloat16 g_ch[(size_t)M_*D_], g_cl[(size_t)M_*D_];
// Raw-input split planes
__device__ __nv_bfloat16 g_rqh[(size_t)M_*D_], g_rql[(size_t)M_*D_];
__device__ __nv_bfloat16 g_rkh[(size_t)M_*D_], g_rkl[(size_t)M_*D_];
__device__ __nv_bfloat16 g_rvh[(size_t)M_*D_], g_rvl[(size_t)M_*D_];
// Weight split planes (wq, wk, wv, wo)
__device__ __nv_bfloat16 g_wh[4][(size_t)D_*D_], g_wl[4][(size_t)D_*D_];

// ---------------------------------------------------------------------------
__device__ __forceinline__ uint32_t cvta_s(const void* p) {
    return (uint32_t)__cvta_generic_to_shared(p);
}
__device__ __forceinline__ void cpa16(uint32_t dst, const void* src) {
    asm volatile("cp.async.cg.shared.global [%0], [%1], 16;" :: "r"(dst), "l"(src));
}
__device__ __forceinline__ void ldsm4(uint32_t r[4], uint32_t a) {
    asm volatile("ldmatrix.sync.aligned.m8n8.x4.shared.b16 {%0,%1,%2,%3}, [%4];"
        : "=r"(r[0]), "=r"(r[1]), "=r"(r[2]), "=r"(r[3]) : "r"(a));
}
__device__ __forceinline__ void ldsm4t(uint32_t r[4], uint32_t a) {
    asm volatile("ldmatrix.sync.aligned.m8n8.x4.trans.shared.b16 {%0,%1,%2,%3}, [%4];"
        : "=r"(r[0]), "=r"(r[1]), "=r"(r[2]), "=r"(r[3]) : "r"(a));
}
__device__ __forceinline__ void mma_bf(float c[4], const uint32_t a[4],
                                       uint32_t b0, uint32_t b1) {
    asm volatile("mma.sync.aligned.m16n8k16.row.col.f32.bf16.bf16.f32 "
        "{%0,%1,%2,%3},{%4,%5,%6,%7},{%8,%9},{%0,%1,%2,%3};"
        : "+f"(c[0]), "+f"(c[1]), "+f"(c[2]), "+f"(c[3])
        : "r"(a[0]), "r"(a[1]), "r"(a[2]), "r"(a[3]), "r"(b0), "r"(b1));
}
__device__ __forceinline__ void split_bf(float x, __nv_bfloat16& h, __nv_bfloat16& l) {
    h = __float2bfloat16(x);
    l = __float2bfloat16(x - __bfloat162float(h));
}

// ---------------------------------------------------------------------------
// Pre-split: fp32 -> bf16 hi/lo planes
// ---------------------------------------------------------------------------
__global__ void __launch_bounds__(256)
split_kernel(const float* __restrict__ in, __nv_bfloat16* __restrict__ hi,
             __nv_bfloat16* __restrict__ lo, int n4)
{
    int i = blockIdx.x * blockDim.x + threadIdx.x;
    if (i >= n4) return;
    float4 v = ((const float4*)in)[i];
    __nv_bfloat16 h0,l0,h1,l1,h2,l2,h3,l3;
    split_bf(v.x,h0,l0); split_bf(v.y,h1,l1);
    split_bf(v.z,h2,l2); split_bf(v.w,h3,l3);
    ((__nv_bfloat162*)hi)[2*i]   = __halves2bfloat162(h0,h1);
    ((__nv_bfloat162*)hi)[2*i+1] = __halves2bfloat162(h2,h3);
    ((__nv_bfloat162*)lo)[2*i]   = __halves2bfloat162(l0,l1);
    ((__nv_bfloat162*)lo)[2*i+1] = __halves2bfloat162(l2,l3);
}

// ---------------------------------------------------------------------------
// Big GEMM v3: 128 threads, 4 warps, CTA tile 128x128, warp tile 64x64.
// MMA:ldsm ratio 6 (vs 4 in v2) -> smem crossbar no longer binding.
// C = epi(A @ W + bias); A, W as bf16 hi/lo planes; cp.async 2-stage.
// smem stage (elems): Ah[128*40]@0, Al@5120, Bh[32*136]@10240, Bl@14592
// ---------------------------------------------------------------------------
#define STG_ 18944
template<bool DO_BN, bool SPLIT_OUT>
__global__ void __launch_bounds__(128, 2)
gemm_tc3(const __nv_bfloat16* __restrict__ Ah, const __nv_bfloat16* __restrict__ Al,
         const __nv_bfloat16* __restrict__ Wh, const __nv_bfloat16* __restrict__ Wl,
         const float* __restrict__ bias,
         const float* __restrict__ gam, const float* __restrict__ bet,
         const float* __restrict__ mmean, const float* __restrict__ mvar,
         float* __restrict__ Cf,
         __nv_bfloat16* __restrict__ Chg, __nv_bfloat16* __restrict__ Clg)
{
    extern __shared__ __align__(16) __nv_bfloat16 sm2[];
    const int tid = threadIdx.x, lane = tid & 31, warp = tid >> 5;
    const int brow = blockIdx.y * 128, bcol = blockIdx.x * 128;

    auto issue = [&](int slab, int buf) {
        __nv_bfloat16* st = sm2 + buf * STG_;
        const int ks = slab * 32;
        #pragma unroll
        for (int p = 0; p < 4; p++) {
            int c = tid + 128 * p;             // 0..511
            int r = c >> 2, q = (c & 3) * 8;   // A: row 0..127, elem 0..24
            const size_t ga = (size_t)(brow + r) * D_ + ks + q;
            cpa16(cvta_s(&st[r*40 + q]),        &Ah[ga]);
            cpa16(cvta_s(&st[5120 + r*40 + q]), &Al[ga]);
        }
        #pragma unroll
        for (int p = 0; p < 4; p++) {
            int c = tid + 128 * p;             // 0..511
            int r = c >> 4, q = (c & 15) * 8;  // B: row 0..31, elem 0..120
            const size_t gb = (size_t)(ks + r) * D_ + bcol + q;
            cpa16(cvta_s(&st[10240 + r*136 + q]), &Wh[gb]);
            cpa16(cvta_s(&st[14592 + r*136 + q]), &Wl[gb]);
        }
        asm volatile("cp.async.commit_group;");
    };

    const int wm = warp >> 1, wn = warp & 1;
    const int m0 = wm * 64, n0 = wn * 64;

    float acc[4][8][4];
    #pragma unroll
    for (int i = 0; i < 4; i++)
        #pragma unroll
        for (int j = 0; j < 8; j++)
            #pragma unroll
            for (int q = 0; q < 4; q++) acc[i][j][q] = 0.f;

    issue(0, 0);
    for (int s = 0; s < 32; s++) {
        const int buf = s & 1;
        if (s + 1 < 32) {
            issue(s + 1, buf ^ 1);
            asm volatile("cp.async.wait_group 1;");
        } else {
            asm volatile("cp.async.wait_group 0;");
        }
        __syncthreads();

        const __nv_bfloat16* sAh = sm2 + buf * STG_;
        const __nv_bfloat16* sAl = sAh + 5120;
        const __nv_bfloat16* sBh = sAh + 10240;
        const __nv_bfloat16* sBl = sAh + 14592;

        #pragma unroll
        for (int kk = 0; kk < 32; kk += 16) {
            uint32_t ah[4][4], al[4][4];
            #pragma unroll
            for (int mi = 0; mi < 4; mi++) {
                int off = (m0 + mi*16 + (lane & 15)) * 40 + kk + ((lane >> 4) << 3);
                ldsm4(ah[mi], cvta_s(&sAh[off]));
                ldsm4(al[mi], cvta_s(&sAl[off]));
            }
            #pragma unroll
            for (int nj = 0; nj < 4; nj++) {
                uint32_t bh[4], bl[4];
                int off = (kk + (lane & 15)) * 136 + n0 + nj*16 + ((lane >> 4) << 3);
                ldsm4t(bh, cvta_s(&sBh[off]));
                ldsm4t(bl, cvta_s(&sBl[off]));
                #pragma unroll
                for (int mi = 0; mi < 4; mi++) {
                    mma_bf(acc[mi][2*nj],   ah[mi], bh[0], bh[1]);
                    mma_bf(acc[mi][2*nj],   ah[mi], bl[0], bl[1]);
                    mma_bf(acc[mi][2*nj],   al[mi], bh[0], bh[1]);
                    mma_bf(acc[mi][2*nj+1], ah[mi], bh[2], bh[3]);
                    mma_bf(acc[mi][2*nj+1], ah[mi], bl[2], bl[3]);
                    mma_bf(acc[mi][2*nj+1], al[mi], bh[2], bh[3]);
                }
            }
        }
        __syncthreads();
    }

    // epilogue (per-warp 64x64 fragment writes)
    #pragma unroll
    for (int mi = 0; mi < 4; mi++) {
        int r0 = brow + m0 + mi*16 + (lane >> 2);
        #pragma unroll
        for (int nj = 0; nj < 8; nj++) {
            int c = bcol + n0 + nj*8 + (lane & 3)*2;
            float b0v = bias[c], b1v = bias[c+1];
            float sc0 = 1.f, sh0 = 0.f, sc1 = 1.f, sh1 = 0.f;
            if (DO_BN) {
                sc0 = gam[c]   * rsqrtf(mvar[c]   + 1e-3f); sh0 = bet[c]   - mmean[c]   * sc0;
                sc1 = gam[c+1] * rsqrtf(mvar[c+1] + 1e-3f); sh1 = bet[c+1] - mmean[c+1] * sc1;
            }
            float y00 = fmaxf(acc[mi][nj][0] + b0v, 0.f);
            float y01 = fmaxf(acc[mi][nj][1] + b1v, 0.f);
            float y10 = fmaxf(acc[mi][nj][2] + b0v, 0.f);
            float y11 = fmaxf(acc[mi][nj][3] + b1v, 0.f);
            if (DO_BN) {
                y00 = y00*sc0 + sh0; y01 = y01*sc1 + sh1;
                y10 = y10*sc0 + sh0; y11 = y11*sc1 + sh1;
            }
            if constexpr (SPLIT_OUT) {
                __nv_bfloat16 h0,l0,h1,l1,h2,l2,h3,l3;
                split_bf(y00,h0,l0); split_bf(y01,h1,l1);
                split_bf(y10,h2,l2); split_bf(y11,h3,l3);
                *(__nv_bfloat162*)&Chg[(size_t)r0*D_ + c]     = __halves2bfloat162(h0,h1);
                *(__nv_bfloat162*)&Clg[(size_t)r0*D_ + c]     = __halves2bfloat162(l0,l1);
                *(__nv_bfloat162*)&Chg[(size_t)(r0+8)*D_ + c] = __halves2bfloat162(h2,h3);
                *(__nv_bfloat162*)&Clg[(size_t)(r0+8)*D_ + c] = __halves2bfloat162(l2,l3);
            } else {
                *(float2*)&Cf[(size_t)r0*D_ + c]     = make_float2(y00, y01);
                *(float2*)&Cf[(size_t)(r0+8)*D_ + c] = make_float2(y10, y11);
            }
        }
    }
}

// ---------------------------------------------------------------------------
// scores: per (b,h): (Qh @ Kh^T)*0.125 + mask*(-1e9)  [K=64, single load]
// ---------------------------------------------------------------------------
__global__ void __launch_bounds__(256)
scores_tc(const float* __restrict__ mask, float* __restrict__ attn)
{
    extern __shared__ __align__(16) __nv_bfloat16 sm[];
    __nv_bfloat16* sQh = sm;
    __nv_bfloat16* sQl = sm + 9216;
    __nv_bfloat16* sKh = sm + 18432;
    __nv_bfloat16* sKl = sm + 27648;

    const int bh = blockIdx.z, b = bh >> 4, h = bh & 15;
    const size_t base = (size_t)b * S_ * D_ + h * DH_;
    const int tid = threadIdx.x, lane = tid & 31, warp = tid >> 5;
    const int brow = blockIdx.y * 128, bcol = blockIdx.x * 128;

    #pragma unroll
    for (int p = 0; p < 4; p++) {
        int idx = tid + 256 * p;
        int row = idx >> 3;
        int ch  = (idx & 7) * 8;
        *(uint4*)&sQh[row*72 + ch] = *(const uint4*)&g_qh[base + (size_t)(brow + row)*D_ + ch];
        *(uint4*)&sQl[row*72 + ch] = *(const uint4*)&g_ql[base + (size_t)(brow + row)*D_ + ch];
        *(uint4*)&sKh[row*72 + ch] = *(const uint4*)&g_kh[base + (size_t)(bcol + row)*D_ + ch];
        *(uint4*)&sKl[row*72 + ch] = *(const uint4*)&g_kl[base + (size_t)(bcol + row)*D_ + ch];
    }
    __syncthreads();

    const int wm = warp >> 1, wn = warp & 1;
    const int m0 = wm * 32, n0 = wn * 64;

    float acc[2][8][4];
    #pragma unroll
    for (int i = 0; i < 2; i++)
        #pragma unroll
        for (int j = 0; j < 8; j++)
            #pragma unroll
            for (int q = 0; q < 4; q++) acc[i][j][q] = 0.f;

    #pragma unroll
    for (int kk = 0; kk < 64; kk += 16) {
        uint32_t ah[2][4], al[2][4];
        #pragma unroll
        for (int mi = 0; mi < 2; mi++) {
            int off = (m0 + mi*16 + (lane & 15)) * 72 + kk + ((lane >> 4) << 3);
            ldsm4(ah[mi], cvta_s(&sQh[off]));
            ldsm4(al[mi], cvta_s(&sQl[off]));
        }
        #pragma unroll
        for (int nj = 0; nj < 4; nj++) {
            int nr = n0 + nj*16 + ((lane & 7) | (((lane >> 4) & 1) << 3));
            int off = nr * 72 + kk + (((lane >> 3) & 1) << 3);
            uint32_t bh[4], bl[4];
            ldsm4(bh, cvta_s(&sKh[off]));
            ldsm4(bl, cvta_s(&sKl[off]));
            #pragma unroll
            for (int mi = 0; mi < 2; mi++) {
                mma_bf(acc[mi][2*nj],   ah[mi], bh[0], bh[1]);
                mma_bf(acc[mi][2*nj],   ah[mi], bl[0], bl[1]);
                mma_bf(acc[mi][2*nj],   al[mi], bh[0], bh[1]);
                mma_bf(acc[mi][2*nj+1], ah[mi], bh[2], bh[3]);
                mma_bf(acc[mi][2*nj+1], ah[mi], bl[2], bl[3]);
                mma_bf(acc[mi][2*nj+1], al[mi], bh[2], bh[3]);
            }
        }
    }

    float* outp = attn + (size_t)bh * S_ * S_;
    #pragma unroll
    for (int mi = 0; mi < 2; mi++) {
        int r0 = brow + m0 + mi*16 + (lane >> 2);
        #pragma unroll
        for (int nj = 0; nj < 8; nj++) {
            int c = bcol + n0 + nj*8 + (lane & 3)*2;
            float mv0 = mask[b*S_ + c]     * (-1e9f);
            float mv1 = mask[b*S_ + c + 1] * (-1e9f);
            *(float2*)&outp[(size_t)r0*S_ + c] =
                make_float2(acc[mi][nj][0]*0.125f + mv0, acc[mi][nj][1]*0.125f + mv1);
            *(float2*)&outp[(size_t)(r0+8)*S_ + c] =
                make_float2(acc[mi][nj][2]*0.125f + mv0, acc[mi][nj][3]*0.125f + mv1);
        }
    }
}

// ---------------------------------------------------------------------------
// In-place row softmax (1024 floats/row), 128 threads/row.
// ---------------------------------------------------------------------------
__global__ void __launch_bounds__(128)
softmax_kernel(float* __restrict__ attn)
{
    const size_t row = blockIdx.x;
    float* p = attn + row * (size_t)S_;
    const int tid = threadIdx.x, lane = tid & 31, warp = tid >> 5;

    float v[8];
    float4 a = *reinterpret_cast<const float4*>(&p[tid*8]);
    float4 c = *reinterpret_cast<const float4*>(&p[tid*8 + 4]);
    v[0]=a.x; v[1]=a.y; v[2]=a.z; v[3]=a.w;
    v[4]=c.x; v[5]=c.y; v[6]=c.z; v[7]=c.w;

    float mx = v[0];
    #pragma unroll
    for (int i = 1; i < 8; i++) mx = fmaxf(mx, v[i]);
    #pragma unroll
    for (int o = 16; o; o >>= 1) mx = fmaxf(mx, __shfl_xor_sync(0xffffffffu, mx, o));

    __shared__ float smax[4], ssum[4];
    if (lane == 0) smax[warp] = mx;
    __syncthreads();
    mx = fmaxf(fmaxf(smax[0], smax[1]), fmaxf(smax[2], smax[3]));

    float s = 0.f;
    #pragma unroll
    for (int i = 0; i < 8; i++) { v[i] = __expf(v[i] - mx); s += v[i]; }
    #pragma unroll
    for (int o = 16; o; o >>= 1) s += __shfl_xor_sync(0xffffffffu, s, o);
    if (lane == 0) ssum[warp] = s;
    __syncthreads();
    s = ssum[0] + ssum[1] + ssum[2] + ssum[3];

    const float inv = 1.f / s;
    *(float4*)&p[tid*8]     = make_float4(v[0]*inv, v[1]*inv, v[2]*inv, v[3]*inv);
    *(float4*)&p[tid*8 + 4] = make_float4(v[4]*inv, v[5]*inv, v[6]*inv, v[7]*inv);
}

// ---------------------------------------------------------------------------
// ctx = attn[bh] @ Vh -> split bf16 into g_ch/g_cl ([B,S,D] layout)
// ---------------------------------------------------------------------------
__global__ void __launch_bounds__(256)
ctx_tc(const float* __restrict__ attn)
{
    __shared__ __align__(16) __nv_bfloat16 sAh[128*40], sAl[128*40];
    __shared__ __align__(16) __nv_bfloat16 sBh[32*72],  sBl[32*72];

    const int bh = blockIdx.y, b = bh >> 4, h = bh & 15;
    const float* A = attn + (size_t)bh * S_ * S_;
    const __nv_bfloat16* Vh = g_vh + (size_t)b * S_ * D_ + h * DH_;
    const __nv_bfloat16* Vl = g_vl + (size_t)b * S_ * D_ + h * DH_;

    const int tid = threadIdx.x, lane = tid & 31, warp = tid >> 5;
    const int brow = blockIdx.x * 128;

    float4 stA[4]; uint4 stB[2];
    auto loadG = [&](int ks) {
        #pragma unroll
        for (int p = 0; p < 4; p++) {
            int row = (tid >> 3) + 32 * p, col = (tid & 7) * 4;
            stA[p] = *(const float4*)&A[(size_t)(brow + row) * S_ + ks + col];
        }
        #pragma unroll
        for (int p = 0; p < 2; p++) {
            int idx = tid + 256 * p;
            int r  = (idx & 255) >> 3;
            int ch = (idx & 7) * 8;
            const __nv_bfloat16* src = (idx < 256) ? Vh : Vl;
            stB[p] = *(const uint4*)&src[(size_t)(ks + r) * D_ + ch];
        }
    };
    auto storeS = [&]() {
        #pragma unroll
        for (int p = 0; p < 4; p++) {
            int row = (tid >> 3) + 32 * p, col = (tid & 7) * 4;
            float v[4] = {stA[p].x, stA[p].y, stA[p].z, stA[p].w};
            __nv_bfloat16 hh[4], ll[4];
            #pragma unroll
            for (int i = 0; i < 4; i++) split_bf(v[i], hh[i], ll[i]);
            *(__nv_bfloat162*)&sAh[row*40 + col]     = __halves2bfloat162(hh[0], hh[1]);
            *(__nv_bfloat162*)&sAh[row*40 + col + 2] = __halves2bfloat162(hh[2], hh[3]);
            *(__nv_bfloat162*)&sAl[row*40 + col]     = __halves2bfloat162(ll[0], ll[1]);
            *(__nv_bfloat162*)&sAl[row*40 + col + 2] = __halves2bfloat162(ll[2], ll[3]);
        }
        #pragma unroll
        for (int p = 0; p < 2; p++) {
            int idx = tid + 256 * p;
            int r  = (idx & 255) >> 3;
            int ch = (idx & 7) * 8;
            __nv_bfloat16* dst = (idx < 256) ? sBh : sBl;
            *(uint4*)&dst[r*72 + ch] = stB[p];
        }
    };

    const int wm = warp >> 1, wn = warp & 1;
    const int m0 = wm * 32, n0 = wn * 32;

    float acc[2][4][4];
    #pragma unroll
    for (int i = 0; i < 2; i++)
        #pragma unroll
        for (int j = 0; j < 4; j++)
            #pragma unroll
            for (int q = 0; q < 4; q++) acc[i][j][q] = 0.f;

    loadG(0);
    for (int ks = 0; ks < S_; ks += 32) {
        storeS();
        __syncthreads();
        if (ks + 32 < S_) loadG(ks + 32);

        #pragma unroll
        for (int kk = 0; kk < 32; kk += 16) {
            uint32_t ah[2][4], al[2][4];
            #pragma unroll
            for (int mi = 0; mi < 2; mi++) {
                int off = (m0 + mi*16 + (lane & 15)) * 40 + kk + ((lane >> 4) << 3);
                ldsm4(ah[mi], cvta_s(&sAh[off]));
                ldsm4(al[mi], cvta_s(&sAl[off]));
            }
            #pragma unroll
            for (int nj = 0; nj < 2; nj++) {
                uint32_t bh[4], bl[4];
                int off = (kk + (lane & 15)) * 72 + n0 + nj*16 + ((lane >> 4) << 3);
                ldsm4t(bh, cvta_s(&sBh[off]));
                ldsm4t(bl, cvta_s(&sBl[off]));
                #pragma unroll
                for (int mi = 0; mi < 2; mi++) {
                    mma_bf(acc[mi][2*nj],   ah[mi], bh[0], bh[1]);
                    mma_bf(acc[mi][2*nj],   ah[mi], bl[0], bl[1]);
                    mma_bf(acc[mi][2*nj],   al[mi], bh[0], bh[1]);
                    mma_bf(acc[mi][2*nj+1], ah[mi], bh[2], bh[3]);
                    mma_bf(acc[mi][2*nj+1], ah[mi], bl[2], bl[3]);
                    mma_bf(acc[mi][2*nj+1], al[mi], bh[2], bh[3]);
                }
            }
        }
        __syncthreads();
    }

    __nv_bfloat16* Ch = g_ch + (size_t)b * S_ * D_ + h * DH_;
    __nv_bfloat16* Cl = g_cl + (size_t)b * S_ * D_ + h * DH_;
    #pragma unroll
    for (int mi = 0; mi < 2; mi++) {
        int r0 = brow + m0 + mi*16 + (lane >> 2);
        #pragma unroll
        for (int nj = 0; nj < 4; nj++) {
            int c = n0 + nj*8 + (lane & 3)*2;
            __nv_bfloat16 h0,l0,h1,l1,h2,l2,h3,l3;
            split_bf(acc[mi][nj][0], h0, l0); split_bf(acc[mi][nj][1], h1, l1);
            split_bf(acc[mi][nj][2], h2, l2); split_bf(acc[mi][nj][3], h3, l3);
            *(__nv_bfloat162*)&Ch[(size_t)r0*D_ + c]     = __halves2bfloat162(h0, h1);
            *(__nv_bfloat162*)&Cl[(size_t)r0*D_ + c]     = __halves2bfloat162(l0, l1);
            *(__nv_bfloat162*)&Ch[(size_t)(r0+8)*D_ + c] = __halves2bfloat162(h2, h3);
            *(__nv_bfloat162*)&Cl[(size_t)(r0+8)*D_ + c] = __halves2bfloat162(l2, l3);
        }
    }
}

// ---------------------------------------------------------------------------
extern "C" void kernel_launch(void* const* d_in, const int* in_sizes, int n_in,
                              void* d_out, int out_size)
{
    const float* q    = (const float*)d_in[0];
    const float* k    = (const float*)d_in[1];
    const float* v    = (const float*)d_in[2];
    const float* mask = (const float*)d_in[3];
    const float* wq = (const float*)d_in[4];  const float* bq = (const float*)d_in[5];
    const float* wk = (const float*)d_in[6];  const float* bk = (const float*)d_in[7];
    const float* wv = (const float*)d_in[8];  const float* bv = (const float*)d_in[9];
    const float* wo = (const float*)d_in[10]; const float* bo = (const float*)d_in[11];
    const float* g1 = (const float*)d_in[12]; const float* be1 = (const float*)d_in[13];
    const float* mm1 = (const float*)d_in[14]; const float* mv1 = (const float*)d_in[15];
    const float* g2 = (const float*)d_in[16]; const float* be2 = (const float*)d_in[17];
    const float* mm2 = (const float*)d_in[18]; const float* mv2 = (const float*)d_in[19];
    const float* g3 = (const float*)d_in[20]; const float* be3 = (const float*)d_in[21];
    const float* mm3 = (const float*)d_in[22]; const float* mv3 = (const float*)d_in[23];

    float* out  = (float*)d_out;
    float* attn = out + (size_t)M_ * D_;

    void* p;
    __nv_bfloat16 *qh,*ql,*kh,*kl,*vh,*vl,*ch,*cl;
    __nv_bfloat16 *rqh,*rql,*rkh,*rkl,*rvh,*rvl,*wph,*wpl;
    cudaGetSymbolAddress(&p, g_qh); qh = (__nv_bfloat16*)p;
    cudaGetSymbolAddress(&p, g_ql); ql = (__nv_bfloat16*)p;
    cudaGetSymbolAddress(&p, g_kh); kh = (__nv_bfloat16*)p;
    cudaGetSymbolAddress(&p, g_kl); kl = (__nv_bfloat16*)p;
    cudaGetSymbolAddress(&p, g_vh); vh = (__nv_bfloat16*)p;
    cudaGetSymbolAddress(&p, g_vl); vl = (__nv_bfloat16*)p;
    cudaGetSymbolAddress(&p, g_ch); ch = (__nv_bfloat16*)p;
    cudaGetSymbolAddress(&p, g_cl); cl = (__nv_bfloat16*)p;
    cudaGetSymbolAddress(&p, g_rqh); rqh = (__nv_bfloat16*)p;
    cudaGetSymbolAddress(&p, g_rql); rql = (__nv_bfloat16*)p;
    cudaGetSymbolAddress(&p, g_rkh); rkh = (__nv_bfloat16*)p;
    cudaGetSymbolAddress(&p, g_rkl); rkl = (__nv_bfloat16*)p;
    cudaGetSymbolAddress(&p, g_rvh); rvh = (__nv_bfloat16*)p;
    cudaGetSymbolAddress(&p, g_rvl); rvl = (__nv_bfloat16*)p;
    cudaGetSymbolAddress(&p, g_wh); wph = (__nv_bfloat16*)p;
    cudaGetSymbolAddress(&p, g_wl); wpl = (__nv_bfloat16*)p;

    const size_t WSZ = (size_t)D_ * D_;
    const int n4a = (int)((size_t)M_ * D_ / 4);
    const int n4w = (int)(WSZ / 4);

    split_kernel<<<n4a/256, 256>>>(q, rqh, rql, n4a);
    split_kernel<<<n4a/256, 256>>>(k, rkh, rkl, n4a);
    split_kernel<<<n4a/256, 256>>>(v, rvh, rvl, n4a);
    split_kernel<<<n4w/256, 256>>>(wq, wph + 0*WSZ, wpl + 0*WSZ, n4w);
    split_kernel<<<n4w/256, 256>>>(wk, wph + 1*WSZ, wpl + 1*WSZ, n4w);
    split_kernel<<<n4w/256, 256>>>(wv, wph + 2*WSZ, wpl + 2*WSZ, n4w);
    split_kernel<<<n4w/256, 256>>>(wo, wph + 3*WSZ, wpl + 3*WSZ, n4w);

    cudaFuncSetAttribute(gemm_tc3<true,true>,
        cudaFuncAttributeMaxDynamicSharedMemorySize, 2*STG_*2);
    cudaFuncSetAttribute(gemm_tc3<false,false>,
        cudaFuncAttributeMaxDynamicSharedMemorySize, 2*STG_*2);
    cudaFuncSetAttribute(scores_tc, cudaFuncAttributeMaxDynamicSharedMemorySize, 73728);

    dim3 gp(D_/128, M_/128);   // (8, 64)
    gemm_tc3<true,true><<<gp,128,2*STG_*2>>>(rqh, rql, wph + 0*WSZ, wpl + 0*WSZ,
        bq, g1, be1, mm1, mv1, nullptr, qh, ql);
    gemm_tc3<true,true><<<gp,128,2*STG_*2>>>(rkh, rkl, wph + 1*WSZ, wpl + 1*WSZ,
        bk, g2, be2, mm2, mv2, nullptr, kh, kl);
    gemm_tc3<true,true><<<gp,128,2*STG_*2>>>(rvh, rvl, wph + 2*WSZ, wpl + 2*WSZ,
        bv, g3, be3, mm3, mv3, nullptr, vh, vl);

    scores_tc<<<dim3(8,8,128),256,73728>>>(mask, attn);

    softmax_kernel<<<(unsigned)((size_t)B_*H_*S_),128>>>(attn);

    ctx_tc<<<dim3(8,128),256>>>(attn);

    gemm_tc3<false,false><<<gp,128,2*STG_*2>>>(ch, cl, wph + 3*WSZ, wpl + 3*WSZ,
        bo, nullptr, nullptr, nullptr, nullptr, out, nullptr, nullptr);
}

// round 9
// speedup vs baseline: 1.2092x; 1.0088x over previous
#include <cuda_runtime.h>
#include <cuda_bf16.h>
#include <stdint.h>
#include <math.h>

#define B_  8
#define S_  1024
#define D_  1024
#define H_  16
#define DH_ 64
#define M_  (B_*S_)     // 8192

// Projected split planes
__device__ __nv_bfloat16 g_qh[(size_t)M_*D_], g_ql[(size_t)M_*D_];
__device__ __nv_bfloat16 g_kh[(size_t)M_*D_], g_kl[(size_t)M_*D_];
__device__ __nv_bfloat16 g_vh[(size_t)M_*D_], g_vl[(size_t)M_*D_];
__device__ __nv_bfloat16 g_ch[(size_t)M_*D_], g_cl[(size_t)M_*D_];
// Raw-input split planes
__device__ __nv_bfloat16 g_rqh[(size_t)M_*D_], g_rql[(size_t)M_*D_];
__device__ __nv_bfloat16 g_rkh[(size_t)M_*D_], g_rkl[(size_t)M_*D_];
__device__ __nv_bfloat16 g_rvh[(size_t)M_*D_], g_rvl[(size_t)M_*D_];
// Weight split planes (wq, wk, wv, wo)
__device__ __nv_bfloat16 g_wh[4][(size_t)D_*D_], g_wl[4][(size_t)D_*D_];
// Softmax partials: per (bh, row) x 16 column-ranges (8 bcol-blocks x 2 warp-halves)
__device__ float g_pmax[(size_t)128*1024*16];
__device__ float g_psum[(size_t)128*1024*16];

// ---------------------------------------------------------------------------
__device__ __forceinline__ uint32_t cvta_s(const void* p) {
    return (uint32_t)__cvta_generic_to_shared(p);
}
__device__ __forceinline__ void cpa16(uint32_t dst, const void* src) {
    asm volatile("cp.async.cg.shared.global [%0], [%1], 16;" :: "r"(dst), "l"(src));
}
__device__ __forceinline__ void ldsm4(uint32_t r[4], uint32_t a) {
    asm volatile("ldmatrix.sync.aligned.m8n8.x4.shared.b16 {%0,%1,%2,%3}, [%4];"
        : "=r"(r[0]), "=r"(r[1]), "=r"(r[2]), "=r"(r[3]) : "r"(a));
}
__device__ __forceinline__ void ldsm4t(uint32_t r[4], uint32_t a) {
    asm volatile("ldmatrix.sync.aligned.m8n8.x4.trans.shared.b16 {%0,%1,%2,%3}, [%4];"
        : "=r"(r[0]), "=r"(r[1]), "=r"(r[2]), "=r"(r[3]) : "r"(a));
}
__device__ __forceinline__ void mma_bf(float c[4], const uint32_t a[4],
                                       uint32_t b0, uint32_t b1) {
    asm volatile("mma.sync.aligned.m16n8k16.row.col.f32.bf16.bf16.f32 "
        "{%0,%1,%2,%3},{%4,%5,%6,%7},{%8,%9},{%0,%1,%2,%3};"
        : "+f"(c[0]), "+f"(c[1]), "+f"(c[2]), "+f"(c[3])
        : "r"(a[0]), "r"(a[1]), "r"(a[2]), "r"(a[3]), "r"(b0), "r"(b1));
}
__device__ __forceinline__ void split_bf(float x, __nv_bfloat16& h, __nv_bfloat16& l) {
    h = __float2bfloat16(x);
    l = __float2bfloat16(x - __bfloat162float(h));
}

// ---------------------------------------------------------------------------
// Pre-split: fp32 -> bf16 hi/lo planes
// ---------------------------------------------------------------------------
__global__ void __launch_bounds__(256)
split_kernel(const float* __restrict__ in, __nv_bfloat16* __restrict__ hi,
             __nv_bfloat16* __restrict__ lo, int n4)
{
    int i = blockIdx.x * blockDim.x + threadIdx.x;
    if (i >= n4) return;
    float4 v = ((const float4*)in)[i];
    __nv_bfloat16 h0,l0,h1,l1,h2,l2,h3,l3;
    split_bf(v.x,h0,l0); split_bf(v.y,h1,l1);
    split_bf(v.z,h2,l2); split_bf(v.w,h3,l3);
    ((__nv_bfloat162*)hi)[2*i]   = __halves2bfloat162(h0,h1);
    ((__nv_bfloat162*)hi)[2*i+1] = __halves2bfloat162(h2,h3);
    ((__nv_bfloat162*)lo)[2*i]   = __halves2bfloat162(l0,l1);
    ((__nv_bfloat162*)lo)[2*i+1] = __halves2bfloat162(l2,l3);
}

// ---------------------------------------------------------------------------
// Big GEMM v3 (round-8 WIN): 128 threads, 4 warps, warp tile 64x64.
// ---------------------------------------------------------------------------
#define STG_ 18944
template<bool DO_BN, bool SPLIT_OUT>
__global__ void __launch_bounds__(128, 2)
gemm_tc3(const __nv_bfloat16* __restrict__ Ah, const __nv_bfloat16* __restrict__ Al,
         const __nv_bfloat16* __restrict__ Wh, const __nv_bfloat16* __restrict__ Wl,
         const float* __restrict__ bias,
         const float* __restrict__ gam, const float* __restrict__ bet,
         const float* __restrict__ mmean, const float* __restrict__ mvar,
         float* __restrict__ Cf,
         __nv_bfloat16* __restrict__ Chg, __nv_bfloat16* __restrict__ Clg)
{
    extern __shared__ __align__(16) __nv_bfloat16 sm2[];
    const int tid = threadIdx.x, lane = tid & 31, warp = tid >> 5;
    const int brow = blockIdx.y * 128, bcol = blockIdx.x * 128;

    auto issue = [&](int slab, int buf) {
        __nv_bfloat16* st = sm2 + buf * STG_;
        const int ks = slab * 32;
        #pragma unroll
        for (int p = 0; p < 4; p++) {
            int c = tid + 128 * p;
            int r = c >> 2, q = (c & 3) * 8;
            const size_t ga = (size_t)(brow + r) * D_ + ks + q;
            cpa16(cvta_s(&st[r*40 + q]),        &Ah[ga]);
            cpa16(cvta_s(&st[5120 + r*40 + q]), &Al[ga]);
        }
        #pragma unroll
        for (int p = 0; p < 4; p++) {
            int c = tid + 128 * p;
            int r = c >> 4, q = (c & 15) * 8;
            const size_t gb = (size_t)(ks + r) * D_ + bcol + q;
            cpa16(cvta_s(&st[10240 + r*136 + q]), &Wh[gb]);
            cpa16(cvta_s(&st[14592 + r*136 + q]), &Wl[gb]);
        }
        asm volatile("cp.async.commit_group;");
    };

    const int wm = warp >> 1, wn = warp & 1;
    const int m0 = wm * 64, n0 = wn * 64;

    float acc[4][8][4];
    #pragma unroll
    for (int i = 0; i < 4; i++)
        #pragma unroll
        for (int j = 0; j < 8; j++)
            #pragma unroll
            for (int q = 0; q < 4; q++) acc[i][j][q] = 0.f;

    issue(0, 0);
    for (int s = 0; s < 32; s++) {
        const int buf = s & 1;
        if (s + 1 < 32) {
            issue(s + 1, buf ^ 1);
            asm volatile("cp.async.wait_group 1;");
        } else {
            asm volatile("cp.async.wait_group 0;");
        }
        __syncthreads();

        const __nv_bfloat16* sAh = sm2 + buf * STG_;
        const __nv_bfloat16* sAl = sAh + 5120;
        const __nv_bfloat16* sBh = sAh + 10240;
        const __nv_bfloat16* sBl = sAh + 14592;

        #pragma unroll
        for (int kk = 0; kk < 32; kk += 16) {
            uint32_t ah[4][4], al[4][4];
            #pragma unroll
            for (int mi = 0; mi < 4; mi++) {
                int off = (m0 + mi*16 + (lane & 15)) * 40 + kk + ((lane >> 4) << 3);
                ldsm4(ah[mi], cvta_s(&sAh[off]));
                ldsm4(al[mi], cvta_s(&sAl[off]));
            }
            #pragma unroll
            for (int nj = 0; nj < 4; nj++) {
                uint32_t bh[4], bl[4];
                int off = (kk + (lane & 15)) * 136 + n0 + nj*16 + ((lane >> 4) << 3);
                ldsm4t(bh, cvta_s(&sBh[off]));
                ldsm4t(bl, cvta_s(&sBl[off]));
                #pragma unroll
                for (int mi = 0; mi < 4; mi++) {
                    mma_bf(acc[mi][2*nj],   ah[mi], bh[0], bh[1]);
                    mma_bf(acc[mi][2*nj],   ah[mi], bl[0], bl[1]);
                    mma_bf(acc[mi][2*nj],   al[mi], bh[0], bh[1]);
                    mma_bf(acc[mi][2*nj+1], ah[mi], bh[2], bh[3]);
                    mma_bf(acc[mi][2*nj+1], ah[mi], bl[2], bl[3]);
                    mma_bf(acc[mi][2*nj+1], al[mi], bh[2], bh[3]);
                }
            }
        }
        __syncthreads();
    }

    #pragma unroll
    for (int mi = 0; mi < 4; mi++) {
        int r0 = brow + m0 + mi*16 + (lane >> 2);
        #pragma unroll
        for (int nj = 0; nj < 8; nj++) {
            int c = bcol + n0 + nj*8 + (lane & 3)*2;
            float b0v = bias[c], b1v = bias[c+1];
            float sc0 = 1.f, sh0 = 0.f, sc1 = 1.f, sh1 = 0.f;
            if (DO_BN) {
                sc0 = gam[c]   * rsqrtf(mvar[c]   + 1e-3f); sh0 = bet[c]   - mmean[c]   * sc0;
                sc1 = gam[c+1] * rsqrtf(mvar[c+1] + 1e-3f); sh1 = bet[c+1] - mmean[c+1] * sc1;
            }
            float y00 = fmaxf(acc[mi][nj][0] + b0v, 0.f);
            float y01 = fmaxf(acc[mi][nj][1] + b1v, 0.f);
            float y10 = fmaxf(acc[mi][nj][2] + b0v, 0.f);
            float y11 = fmaxf(acc[mi][nj][3] + b1v, 0.f);
            if (DO_BN) {
                y00 = y00*sc0 + sh0; y01 = y01*sc1 + sh1;
                y10 = y10*sc0 + sh0; y11 = y11*sc1 + sh1;
            }
            if constexpr (SPLIT_OUT) {
                __nv_bfloat16 h0,l0,h1,l1,h2,l2,h3,l3;
                split_bf(y00,h0,l0); split_bf(y01,h1,l1);
                split_bf(y10,h2,l2); split_bf(y11,h3,l3);
                *(__nv_bfloat162*)&Chg[(size_t)r0*D_ + c]     = __halves2bfloat162(h0,h1);
                *(__nv_bfloat162*)&Clg[(size_t)r0*D_ + c]     = __halves2bfloat162(l0,l1);
                *(__nv_bfloat162*)&Chg[(size_t)(r0+8)*D_ + c] = __halves2bfloat162(h2,h3);
                *(__nv_bfloat162*)&Clg[(size_t)(r0+8)*D_ + c] = __halves2bfloat162(l2,l3);
            } else {
                *(float2*)&Cf[(size_t)r0*D_ + c]     = make_float2(y00, y01);
                *(float2*)&Cf[(size_t)(r0+8)*D_ + c] = make_float2(y10, y11);
            }
        }
    }
}

// ---------------------------------------------------------------------------
// scores + per-range softmax partials.
// Writes raw (scaled+masked) scores to attn, and per (row, 64-col range)
// partial max / sum-of-exp into g_pmax/g_psum[bh][row][bcolblk*2 + wn].
// ---------------------------------------------------------------------------
__global__ void __launch_bounds__(256)
scores_tc(const float* __restrict__ mask, float* __restrict__ attn)
{
    extern __shared__ __align__(16) __nv_bfloat16 sm[];
    __nv_bfloat16* sQh = sm;
    __nv_bfloat16* sQl = sm + 9216;
    __nv_bfloat16* sKh = sm + 18432;
    __nv_bfloat16* sKl = sm + 27648;

    const int bh = blockIdx.z, b = bh >> 4, h = bh & 15;
    const size_t base = (size_t)b * S_ * D_ + h * DH_;
    const int tid = threadIdx.x, lane = tid & 31, warp = tid >> 5;
    const int brow = blockIdx.y * 128, bcol = blockIdx.x * 128;

    #pragma unroll
    for (int p = 0; p < 4; p++) {
        int idx = tid + 256 * p;
        int row = idx >> 3;
        int ch  = (idx & 7) * 8;
        *(uint4*)&sQh[row*72 + ch] = *(const uint4*)&g_qh[base + (size_t)(brow + row)*D_ + ch];
        *(uint4*)&sQl[row*72 + ch] = *(const uint4*)&g_ql[base + (size_t)(brow + row)*D_ + ch];
        *(uint4*)&sKh[row*72 + ch] = *(const uint4*)&g_kh[base + (size_t)(bcol + row)*D_ + ch];
        *(uint4*)&sKl[row*72 + ch] = *(const uint4*)&g_kl[base + (size_t)(bcol + row)*D_ + ch];
    }
    __syncthreads();

    const int wm = warp >> 1, wn = warp & 1;
    const int m0 = wm * 32, n0 = wn * 64;

    float acc[2][8][4];
    #pragma unroll
    for (int i = 0; i < 2; i++)
        #pragma unroll
        for (int j = 0; j < 8; j++)
            #pragma unroll
            for (int q = 0; q < 4; q++) acc[i][j][q] = 0.f;

    #pragma unroll
    for (int kk = 0; kk < 64; kk += 16) {
        uint32_t ah[2][4], al[2][4];
        #pragma unroll
        for (int mi = 0; mi < 2; mi++) {
            int off = (m0 + mi*16 + (lane & 15)) * 72 + kk + ((lane >> 4) << 3);
            ldsm4(ah[mi], cvta_s(&sQh[off]));
            ldsm4(al[mi], cvta_s(&sQl[off]));
        }
        #pragma unroll
        for (int nj = 0; nj < 4; nj++) {
            int nr = n0 + nj*16 + ((lane & 7) | (((lane >> 4) & 1) << 3));
            int off = nr * 72 + kk + (((lane >> 3) & 1) << 3);
            uint32_t bh4[4], bl4[4];
            ldsm4(bh4, cvta_s(&sKh[off]));
            ldsm4(bl4, cvta_s(&sKl[off]));
            #pragma unroll
            for (int mi = 0; mi < 2; mi++) {
                mma_bf(acc[mi][2*nj],   ah[mi], bh4[0], bh4[1]);
                mma_bf(acc[mi][2*nj],   ah[mi], bl4[0], bl4[1]);
                mma_bf(acc[mi][2*nj],   al[mi], bh4[0], bh4[1]);
                mma_bf(acc[mi][2*nj+1], ah[mi], bh4[2], bh4[3]);
                mma_bf(acc[mi][2*nj+1], ah[mi], bl4[2], bl4[3]);
                mma_bf(acc[mi][2*nj+1], al[mi], bh4[2], bh4[3]);
            }
        }
    }

    // mask values (cached in regs)
    float mk0[8], mk1[8];
    #pragma unroll
    for (int nj = 0; nj < 8; nj++) {
        int c = bcol + n0 + nj*8 + (lane & 3)*2;
        mk0[nj] = mask[b*S_ + c]     * (-1e9f);
        mk1[nj] = mask[b*S_ + c + 1] * (-1e9f);
    }

    float* outp = attn + (size_t)bh * S_ * S_;
    const int pidx = blockIdx.x * 2 + wn;
    #pragma unroll
    for (int mi = 0; mi < 2; mi++) {
        int r0 = brow + m0 + mi*16 + (lane >> 2);
        float mA = -3.4e38f, mB = -3.4e38f;
        #pragma unroll
        for (int nj = 0; nj < 8; nj++) {
            int c = bcol + n0 + nj*8 + (lane & 3)*2;
            float x0 = fmaf(acc[mi][nj][0], 0.125f, mk0[nj]);
            float x1 = fmaf(acc[mi][nj][1], 0.125f, mk1[nj]);
            float x2 = fmaf(acc[mi][nj][2], 0.125f, mk0[nj]);
            float x3 = fmaf(acc[mi][nj][3], 0.125f, mk1[nj]);
            acc[mi][nj][0] = x0; acc[mi][nj][1] = x1;
            acc[mi][nj][2] = x2; acc[mi][nj][3] = x3;
            *(float2*)&outp[(size_t)r0*S_ + c]     = make_float2(x0, x1);
            *(float2*)&outp[(size_t)(r0+8)*S_ + c] = make_float2(x2, x3);
            mA = fmaxf(mA, fmaxf(x0, x1));
            mB = fmaxf(mB, fmaxf(x2, x3));
        }
        #pragma unroll
        for (int o = 1; o < 4; o <<= 1) {
            mA = fmaxf(mA, __shfl_xor_sync(0xffffffffu, mA, o));
            mB = fmaxf(mB, __shfl_xor_sync(0xffffffffu, mB, o));
        }
        float sA = 0.f, sB = 0.f;
        #pragma unroll
        for (int nj = 0; nj < 8; nj++) {
            sA += __expf(acc[mi][nj][0] - mA) + __expf(acc[mi][nj][1] - mA);
            sB += __expf(acc[mi][nj][2] - mB) + __expf(acc[mi][nj][3] - mB);
        }
        #pragma unroll
        for (int o = 1; o < 4; o <<= 1) {
            sA += __shfl_xor_sync(0xffffffffu, sA, o);
            sB += __shfl_xor_sync(0xffffffffu, sB, o);
        }
        if ((lane & 3) == 0) {
            size_t pa = ((size_t)bh*1024 + r0)*16 + pidx;
            size_t pb = ((size_t)bh*1024 + r0 + 8)*16 + pidx;
            g_pmax[pa] = mA; g_psum[pa] = sA;
            g_pmax[pb] = mB; g_psum[pb] = sB;
        }
    }
}

// ---------------------------------------------------------------------------
// pv_fused = softmax + ctx: combines partials, normalizes raw scores in place
// (writing the final attn output), and computes ctx = P @ V -> split planes.
// Structure identical to the proven ctx_tc pipeline.
// ---------------------------------------------------------------------------
__global__ void __launch_bounds__(256)
pv_fused(float* __restrict__ attn)
{
    __shared__ __align__(16) __nv_bfloat16 sAh[128*40], sAl[128*40];
    __shared__ __align__(16) __nv_bfloat16 sBh[32*72],  sBl[32*72];
    __shared__ float sMx[128], sInv[128];

    const int bh = blockIdx.y, b = bh >> 4, h = bh & 15;
    float* A = attn + (size_t)bh * S_ * S_;
    const __nv_bfloat16* Vh = g_vh + (size_t)b * S_ * D_ + h * DH_;
    const __nv_bfloat16* Vl = g_vl + (size_t)b * S_ * D_ + h * DH_;

    const int tid = threadIdx.x, lane = tid & 31, warp = tid >> 5;
    const int brow = blockIdx.x * 128;

    // prologue: combine 16 softmax partials per row
    if (tid < 128) {
        size_t pb = ((size_t)bh*1024 + brow + tid) * 16;
        float pm[16], ps[16];
        #pragma unroll
        for (int j = 0; j < 4; j++) {
            *(float4*)&pm[j*4] = *(const float4*)&g_pmax[pb + j*4];
            *(float4*)&ps[j*4] = *(const float4*)&g_psum[pb + j*4];
        }
        float mx = pm[0];
        #pragma unroll
        for (int j = 1; j < 16; j++) mx = fmaxf(mx, pm[j]);
        float s = 0.f;
        #pragma unroll
        for (int j = 0; j < 16; j++) s += ps[j] * __expf(pm[j] - mx);
        sMx[tid] = mx; sInv[tid] = 1.f / s;
    }
    __syncthreads();

    float4 stA[4]; uint4 stB[2];
    auto loadG = [&](int ks) {
        #pragma unroll
        for (int p = 0; p < 4; p++) {
            int row = (tid >> 3) + 32 * p, col = (tid & 7) * 4;
            stA[p] = *(const float4*)&A[(size_t)(brow + row) * S_ + ks + col];
        }
        #pragma unroll
        for (int p = 0; p < 2; p++) {
            int idx = tid + 256 * p;
            int r  = (idx & 255) >> 3;
            int ch = (idx & 7) * 8;
            const __nv_bfloat16* src = (idx < 256) ? Vh : Vl;
            stB[p] = *(const uint4*)&src[(size_t)(ks + r) * D_ + ch];
        }
    };
    auto storeS = [&](int ks) {
        #pragma unroll
        for (int p = 0; p < 4; p++) {
            int row = (tid >> 3) + 32 * p, col = (tid & 7) * 4;
            const float mx = sMx[row], inv = sInv[row];
            float v[4] = {stA[p].x, stA[p].y, stA[p].z, stA[p].w};
            #pragma unroll
            for (int i = 0; i < 4; i++) v[i] = __expf(v[i] - mx) * inv;
            // write normalized attn (final output) in place
            *(float4*)&A[(size_t)(brow + row) * S_ + ks + col] =
                make_float4(v[0], v[1], v[2], v[3]);
            __nv_bfloat16 hh[4], ll[4];
            #pragma unroll
            for (int i = 0; i < 4; i++) split_bf(v[i], hh[i], ll[i]);
            *(__nv_bfloat162*)&sAh[row*40 + col]     = __halves2bfloat162(hh[0], hh[1]);
            *(__nv_bfloat162*)&sAh[row*40 + col + 2] = __halves2bfloat162(hh[2], hh[3]);
            *(__nv_bfloat162*)&sAl[row*40 + col]     = __halves2bfloat162(ll[0], ll[1]);
            *(__nv_bfloat162*)&sAl[row*40 + col + 2] = __halves2bfloat162(ll[2], ll[3]);
        }
        #pragma unroll
        for (int p = 0; p < 2; p++) {
            int idx = tid + 256 * p;
            int r  = (idx & 255) >> 3;
            int ch = (idx & 7) * 8;
            __nv_bfloat16* dst = (idx < 256) ? sBh : sBl;
            *(uint4*)&dst[r*72 + ch] = stB[p];
        }
    };

    const int wm = warp >> 1, wn = warp & 1;
    const int m0 = wm * 32, n0 = wn * 32;

    float acc[2][4][4];
    #pragma unroll
    for (int i = 0; i < 2; i++)
        #pragma unroll
        for (int j = 0; j < 4; j++)
            #pragma unroll
            for (int q = 0; q < 4; q++) acc[i][j][q] = 0.f;

    loadG(0);
    for (int ks = 0; ks < S_; ks += 32) {
        storeS(ks);
        __syncthreads();
        if (ks + 32 < S_) loadG(ks + 32);

        #pragma unroll
        for (int kk = 0; kk < 32; kk += 16) {
            uint32_t ah[2][4], al[2][4];
            #pragma unroll
            for (int mi = 0; mi < 2; mi++) {
                int off = (m0 + mi*16 + (lane & 15)) * 40 + kk + ((lane >> 4) << 3);
                ldsm4(ah[mi], cvta_s(&sAh[off]));
                ldsm4(al[mi], cvta_s(&sAl[off]));
            }
            #pragma unroll
            for (int nj = 0; nj < 2; nj++) {
                uint32_t bh4[4], bl4[4];
                int off = (kk + (lane & 15)) * 72 + n0 + nj*16 + ((lane >> 4) << 3);
                ldsm4t(bh4, cvta_s(&sBh[off]));
                ldsm4t(bl4, cvta_s(&sBl[off]));
                #pragma unroll
                for (int mi = 0; mi < 2; mi++) {
                    mma_bf(acc[mi][2*nj],   ah[mi], bh4[0], bh4[1]);
                    mma_bf(acc[mi][2*nj],   ah[mi], bl4[0], bl4[1]);
                    mma_bf(acc[mi][2*nj],   al[mi], bh4[0], bh4[1]);
                    mma_bf(acc[mi][2*nj+1], ah[mi], bh4[2], bh4[3]);
                    mma_bf(acc[mi][2*nj+1], ah[mi], bl4[2], bl4[3]);
                    mma_bf(acc[mi][2*nj+1], al[mi], bh4[2], bh4[3]);
                }
            }
        }
        __syncthreads();
    }

    __nv_bfloat16* Ch = g_ch + (size_t)b * S_ * D_ + h * DH_;
    __nv_bfloat16* Cl = g_cl + (size_t)b * S_ * D_ + h * DH_;
    #pragma unroll
    for (int mi = 0; mi < 2; mi++) {
        int r0 = brow + m0 + mi*16 + (lane >> 2);
        #pragma unroll
        for (int nj = 0; nj < 4; nj++) {
            int c = n0 + nj*8 + (lane & 3)*2;
            __nv_bfloat16 h0,l0,h1,l1,h2,l2,h3,l3;
            split_bf(acc[mi][nj][0], h0, l0); split_bf(acc[mi][nj][1], h1, l1);
            split_bf(acc[mi][nj][2], h2, l2); split_bf(acc[mi][nj][3], h3, l3);
            *(__nv_bfloat162*)&Ch[(size_t)r0*D_ + c]     = __halves2bfloat162(h0, h1);
            *(__nv_bfloat162*)&Cl[(size_t)r0*D_ + c]     = __halves2bfloat162(l0, l1);
            *(__nv_bfloat162*)&Ch[(size_t)(r0+8)*D_ + c] = __halves2bfloat162(h2, h3);
            *(__nv_bfloat162*)&Cl[(size_t)(r0+8)*D_ + c] = __halves2bfloat162(l2, l3);
        }
    }
}

// ---------------------------------------------------------------------------
extern "C" void kernel_launch(void* const* d_in, const int* in_sizes, int n_in,
                              void* d_out, int out_size)
{
    const float* q    = (const float*)d_in[0];
    const float* k    = (const float*)d_in[1];
    const float* v    = (const float*)d_in[2];
    const float* mask = (const float*)d_in[3];
    const float* wq = (const float*)d_in[4];  const float* bq = (const float*)d_in[5];
    const float* wk = (const float*)d_in[6];  const float* bk = (const float*)d_in[7];
    const float* wv = (const float*)d_in[8];  const float* bv = (const float*)d_in[9];
    const float* wo = (const float*)d_in[10]; const float* bo = (const float*)d_in[11];
    const float* g1 = (const float*)d_in[12]; const float* be1 = (const float*)d_in[13];
    const float* mm1 = (const float*)d_in[14]; const float* mv1 = (const float*)d_in[15];
    const float* g2 = (const float*)d_in[16]; const float* be2 = (const float*)d_in[17];
    const float* mm2 = (const float*)d_in[18]; const float* mv2 = (const float*)d_in[19];
    const float* g3 = (const float*)d_in[20]; const float* be3 = (const float*)d_in[21];
    const float* mm3 = (const float*)d_in[22]; const float* mv3 = (const float*)d_in[23];

    float* out  = (float*)d_out;
    float* attn = out + (size_t)M_ * D_;

    void* p;
    __nv_bfloat16 *qh,*ql,*kh,*kl,*vh,*vl,*ch,*cl;
    __nv_bfloat16 *rqh,*rql,*rkh,*rkl,*rvh,*rvl,*wph,*wpl;
    cudaGetSymbolAddress(&p, g_qh); qh = (__nv_bfloat16*)p;
    cudaGetSymbolAddress(&p, g_ql); ql = (__nv_bfloat16*)p;
    cudaGetSymbolAddress(&p, g_kh); kh = (__nv_bfloat16*)p;
    cudaGetSymbolAddress(&p, g_kl); kl = (__nv_bfloat16*)p;
    cudaGetSymbolAddress(&p, g_vh); vh = (__nv_bfloat16*)p;
    cudaGetSymbolAddress(&p, g_vl); vl = (__nv_bfloat16*)p;
    cudaGetSymbolAddress(&p, g_ch); ch = (__nv_bfloat16*)p;
    cudaGetSymbolAddress(&p, g_cl); cl = (__nv_bfloat16*)p;
    cudaGetSymbolAddress(&p, g_rqh); rqh = (__nv_bfloat16*)p;
    cudaGetSymbolAddress(&p, g_rql); rql = (__nv_bfloat16*)p;
    cudaGetSymbolAddress(&p, g_rkh); rkh = (__nv_bfloat16*)p;
    cudaGetSymbolAddress(&p, g_rkl); rkl = (__nv_bfloat16*)p;
    cudaGetSymbolAddress(&p, g_rvh); rvh = (__nv_bfloat16*)p;
    cudaGetSymbolAddress(&p, g_rvl); rvl = (__nv_bfloat16*)p;
    cudaGetSymbolAddress(&p, g_wh); wph = (__nv_bfloat16*)p;
    cudaGetSymbolAddress(&p, g_wl); wpl = (__nv_bfloat16*)p;

    const size_t WSZ = (size_t)D_ * D_;
    const int n4a = (int)((size_t)M_ * D_ / 4);
    const int n4w = (int)(WSZ / 4);

    split_kernel<<<n4a/256, 256>>>(q, rqh, rql, n4a);
    split_kernel<<<n4a/256, 256>>>(k, rkh, rkl, n4a);
    split_kernel<<<n4a/256, 256>>>(v, rvh, rvl, n4a);
    split_kernel<<<n4w/256, 256>>>(wq, wph + 0*WSZ, wpl + 0*WSZ, n4w);
    split_kernel<<<n4w/256, 256>>>(wk, wph + 1*WSZ, wpl + 1*WSZ, n4w);
    split_kernel<<<n4w/256, 256>>>(wv, wph + 2*WSZ, wpl + 2*WSZ, n4w);
    split_kernel<<<n4w/256, 256>>>(wo, wph + 3*WSZ, wpl + 3*WSZ, n4w);

    cudaFuncSetAttribute(gemm_tc3<true,true>,
        cudaFuncAttributeMaxDynamicSharedMemorySize, 2*STG_*2);
    cudaFuncSetAttribute(gemm_tc3<false,false>,
        cudaFuncAttributeMaxDynamicSharedMemorySize, 2*STG_*2);
    cudaFuncSetAttribute(scores_tc, cudaFuncAttributeMaxDynamicSharedMemorySize, 73728);

    dim3 gp(D_/128, M_/128);   // (8, 64)
    gemm_tc3<true,true><<<gp,128,2*STG_*2>>>(rqh, rql, wph + 0*WSZ, wpl + 0*WSZ,
        bq, g1, be1, mm1, mv1, nullptr, qh, ql);
    gemm_tc3<true,true><<<gp,128,2*STG_*2>>>(rkh, rkl, wph + 1*WSZ, wpl + 1*WSZ,
        bk, g2, be2, mm2, mv2, nullptr, kh, kl);
    gemm_tc3<true,true><<<gp,128,2*STG_*2>>>(rvh, rvl, wph + 2*WSZ, wpl + 2*WSZ,
        bv, g3, be3, mm3, mv3, nullptr, vh, vl);

    scores_tc<<<dim3(8,8,128),256,73728>>>(mask, attn);

    pv_fused<<<dim3(8,128),256>>>(attn);

    gemm_tc3<false,false><<<gp,128,2*STG_*2>>>(ch, cl, wph + 3*WSZ, wpl + 3*WSZ,
        bo, nullptr, nullptr, nullptr, nullptr, out, nullptr, nullptr);
}